// round 5
// baseline (speedup 1.0000x reference)
#include <cuda_runtime.h>
#include <math_constants.h>

#define SEQ    2048
#define DMODEL 4096
#define NH     32
#define NKV    8
#define HDIM   128
#define KVDIM  (NKV*HDIM)   // 1024

// Scratch (no allocation allowed) — ~84 MB total
__device__ float g_q[SEQ * DMODEL];
__device__ float g_k[SEQ * KVDIM];
__device__ float g_v[SEQ * KVDIM];
__device__ float g_att[SEQ * DMODEL];

// ---------------------------------------------------------------------------
// Tiled fp32 GEMM: C[M,N] = A[M,K] @ B[K,N], row-major, M from grid.y*128.
// 128x128 tile, BK=8, 256 threads, 8x8 per-thread microtile.
// ---------------------------------------------------------------------------
template <int N, int K>
__global__ __launch_bounds__(256) void sgemm_kernel(const float* __restrict__ A,
                                                    const float* __restrict__ B,
                                                    float* __restrict__ C) {
    __shared__ float As[8][128];
    __shared__ float Bs[8][128];

    const int tid = threadIdx.x;
    const int bx = blockIdx.x, by = blockIdx.y;
    const int tr = (tid >> 4) << 3;        // tile row base (0..120)
    const int tc = (tid & 15) << 3;        // tile col base
    const int arow = tid >> 1;             // 0..127
    const int ak   = (tid & 1) << 2;       // 0 or 4
    const int brow = tid >> 5;             // 0..7
    const int bcol = (tid & 31) << 2;      // 0..124

    const float* Aptr = A + ((size_t)(by * 128 + arow)) * K + ak;
    const float* Bptr = B + (size_t)brow * N + bx * 128 + bcol;

    float acc[8][8];
#pragma unroll
    for (int i = 0; i < 8; i++)
#pragma unroll
        for (int j = 0; j < 8; j++) acc[i][j] = 0.f;

    for (int kt = 0; kt < K; kt += 8) {
        float4 av = *(const float4*)(Aptr + kt);
        float4 bv = *(const float4*)(Bptr + (size_t)kt * N);
        As[ak + 0][arow] = av.x;
        As[ak + 1][arow] = av.y;
        As[ak + 2][arow] = av.z;
        As[ak + 3][arow] = av.w;
        *(float4*)&Bs[brow][bcol] = bv;
        __syncthreads();
#pragma unroll
        for (int k = 0; k < 8; k++) {
            float a[8], b[8];
            *(float4*)&a[0] = *(const float4*)&As[k][tr];
            *(float4*)&a[4] = *(const float4*)&As[k][tr + 4];
            *(float4*)&b[0] = *(const float4*)&Bs[k][tc];
            *(float4*)&b[4] = *(const float4*)&Bs[k][tc + 4];
#pragma unroll
            for (int i = 0; i < 8; i++)
#pragma unroll
                for (int j = 0; j < 8; j++) acc[i][j] += a[i] * b[j];
        }
        __syncthreads();
    }

    float* Cptr = C + ((size_t)(by * 128 + tr)) * N + bx * 128 + tc;
#pragma unroll
    for (int i = 0; i < 8; i++) {
        *(float4*)&Cptr[(size_t)i * N]     = make_float4(acc[i][0], acc[i][1], acc[i][2], acc[i][3]);
        *(float4*)&Cptr[(size_t)i * N + 4] = make_float4(acc[i][4], acc[i][5], acc[i][6], acc[i][7]);
    }
}

// ---------------------------------------------------------------------------
// RoPE (interleaved pairs): t[s, h, 2d], t[s, h, 2d+1] rotated by (cos,sin)[s,d]
// ---------------------------------------------------------------------------
__global__ void rope_kernel(float* __restrict__ t, const float* __restrict__ cs,
                            const float* __restrict__ sn, int nheads) {
    int idx = blockIdx.x * blockDim.x + threadIdx.x;
    int total = SEQ * nheads * (HDIM / 2);
    if (idx >= total) return;
    int d = idx & 63;
    int h = (idx >> 6) % nheads;
    int s = idx / (64 * nheads);
    float c = cs[s * 64 + d];
    float si = sn[s * 64 + d];
    float2* p = (float2*)(t + ((size_t)s * nheads + h) * HDIM) + d;
    float2 v = *p;
    *p = make_float2(v.x * c - v.y * si, v.y * c + v.x * si);
}

// ---------------------------------------------------------------------------
// Flash attention, fp32. Grid: (SEQ/64 query tiles, NH heads). 256 threads.
// GQA mapping per reference _repeat_kv: q head h -> kv head (h % NKV).
// Thread (ty=tid/16, tx=tid%16): S rows r=ty*4+i, S cols c=tx+16j,
// O cols d=tx*8..tx*8+7. Odd pitch 129 on Qs/Ks -> conflict-free QK^T loads.
// ---------------------------------------------------------------------------
__global__ __launch_bounds__(256) void flash_kernel() {
    extern __shared__ float sm[];
    float* Qs = sm;                 // 64 x 129
    float* Ks = Qs + 64 * 129;      // 64 x 129
    float* Vs = Ks + 64 * 129;      // 64 x 128
    float* Ps = Vs + 64 * 128;      // 64 x 65

    const int qt = blockIdx.x;
    const int h = blockIdx.y;
    const int kvh = h & (NKV - 1);
    const int tid = threadIdx.x;
    const int ty = tid >> 4, tx = tid & 15;
    const float scale = 0.08838834764831845f;  // 1/sqrt(128)

    // Load + pre-scale Q tile (64 x 128)
#pragma unroll
    for (int i = 0; i < 8; i++) {
        int fi = i * 256 + tid;
        int r = fi >> 5, c = (fi & 31) << 2;
        float4 q4 = *(const float4*)&g_q[((size_t)(qt * 64 + r)) * DMODEL + h * HDIM + c];
        float* dq = &Qs[r * 129 + c];
        dq[0] = q4.x * scale; dq[1] = q4.y * scale;
        dq[2] = q4.z * scale; dq[3] = q4.w * scale;
    }

    float o[4][8];
    float m[4], l[4];
#pragma unroll
    for (int i = 0; i < 4; i++) {
        m[i] = -CUDART_INF_F;
        l[i] = 0.f;
#pragma unroll
        for (int j = 0; j < 8; j++) o[i][j] = 0.f;
    }

    for (int kt = 0; kt <= qt; kt++) {
        __syncthreads();  // previous PV reads of Vs / first-iter Qs writes done
#pragma unroll
        for (int i = 0; i < 8; i++) {
            int fi = i * 256 + tid;
            int r = fi >> 5, c = (fi & 31) << 2;
            size_t gidx = ((size_t)(kt * 64 + r)) * KVDIM + kvh * HDIM + c;
            float4 k4 = *(const float4*)&g_k[gidx];
            float* dk = &Ks[r * 129 + c];
            dk[0] = k4.x; dk[1] = k4.y; dk[2] = k4.z; dk[3] = k4.w;
            *(float4*)&Vs[r * 128 + c] = *(const float4*)&g_v[gidx];
        }
        __syncthreads();

        // S = Q K^T (4x4 per thread)
        float s[4][4];
#pragma unroll
        for (int i = 0; i < 4; i++)
#pragma unroll
            for (int j = 0; j < 4; j++) s[i][j] = 0.f;

        const float* q0 = &Qs[(ty * 4 + 0) * 129];
        const float* q1 = q0 + 129;
        const float* q2 = q1 + 129;
        const float* q3 = q2 + 129;
        const float* k0 = &Ks[(tx + 0) * 129];
        const float* k1 = &Ks[(tx + 16) * 129];
        const float* k2 = &Ks[(tx + 32) * 129];
        const float* k3 = &Ks[(tx + 48) * 129];
#pragma unroll 8
        for (int d = 0; d < 128; d++) {
            float a0 = q0[d], a1 = q1[d], a2 = q2[d], a3 = q3[d];
            float b0 = k0[d], b1 = k1[d], b2 = k2[d], b3 = k3[d];
            s[0][0] += a0 * b0; s[0][1] += a0 * b1; s[0][2] += a0 * b2; s[0][3] += a0 * b3;
            s[1][0] += a1 * b0; s[1][1] += a1 * b1; s[1][2] += a1 * b2; s[1][3] += a1 * b3;
            s[2][0] += a2 * b0; s[2][1] += a2 * b1; s[2][2] += a2 * b2; s[2][3] += a2 * b3;
            s[3][0] += a3 * b0; s[3][1] += a3 * b1; s[3][2] += a3 * b2; s[3][3] += a3 * b3;
        }

        if (kt == qt) {  // causal mask on diagonal tile
#pragma unroll
            for (int i = 0; i < 4; i++)
#pragma unroll
                for (int j = 0; j < 4; j++)
                    if (tx + 16 * j > ty * 4 + i) s[i][j] = -CUDART_INF_F;
        }

        // Online softmax per row (row's 16 owners = contiguous half-warp)
#pragma unroll
        for (int i = 0; i < 4; i++) {
            float mx = fmaxf(fmaxf(s[i][0], s[i][1]), fmaxf(s[i][2], s[i][3]));
            mx = fmaxf(mx, __shfl_xor_sync(0xffffffffu, mx, 1, 16));
            mx = fmaxf(mx, __shfl_xor_sync(0xffffffffu, mx, 2, 16));
            mx = fmaxf(mx, __shfl_xor_sync(0xffffffffu, mx, 4, 16));
            mx = fmaxf(mx, __shfl_xor_sync(0xffffffffu, mx, 8, 16));
            float mn = fmaxf(m[i], mx);
            float corr = __expf(m[i] - mn);
            m[i] = mn;
            float sum = 0.f;
#pragma unroll
            for (int j = 0; j < 4; j++) {
                float p = __expf(s[i][j] - mn);
                s[i][j] = p;
                sum += p;
            }
            sum += __shfl_xor_sync(0xffffffffu, sum, 1, 16);
            sum += __shfl_xor_sync(0xffffffffu, sum, 2, 16);
            sum += __shfl_xor_sync(0xffffffffu, sum, 4, 16);
            sum += __shfl_xor_sync(0xffffffffu, sum, 8, 16);
            l[i] = l[i] * corr + sum;
#pragma unroll
            for (int j = 0; j < 8; j++) o[i][j] *= corr;
            float* pr = &Ps[(ty * 4 + i) * 65];
            pr[tx] = s[i][0];
            pr[tx + 16] = s[i][1];
            pr[tx + 32] = s[i][2];
            pr[tx + 48] = s[i][3];
        }
        __syncthreads();

        // O += P @ V
        const float* vb = &Vs[tx * 8];
        const float* p0r = &Ps[(ty * 4 + 0) * 65];
        const float* p1r = p0r + 65;
        const float* p2r = p1r + 65;
        const float* p3r = p2r + 65;
#pragma unroll 4
        for (int c = 0; c < 64; c++) {
            float p0 = p0r[c], p1 = p1r[c], p2 = p2r[c], p3 = p3r[c];
            float4 va = *(const float4*)&vb[c * 128];
            float4 vbb = *(const float4*)&vb[c * 128 + 4];
            o[0][0] += p0 * va.x; o[0][1] += p0 * va.y; o[0][2] += p0 * va.z; o[0][3] += p0 * va.w;
            o[0][4] += p0 * vbb.x; o[0][5] += p0 * vbb.y; o[0][6] += p0 * vbb.z; o[0][7] += p0 * vbb.w;
            o[1][0] += p1 * va.x; o[1][1] += p1 * va.y; o[1][2] += p1 * va.z; o[1][3] += p1 * va.w;
            o[1][4] += p1 * vbb.x; o[1][5] += p1 * vbb.y; o[1][6] += p1 * vbb.z; o[1][7] += p1 * vbb.w;
            o[2][0] += p2 * va.x; o[2][1] += p2 * va.y; o[2][2] += p2 * va.z; o[2][3] += p2 * va.w;
            o[2][4] += p2 * vbb.x; o[2][5] += p2 * vbb.y; o[2][6] += p2 * vbb.z; o[2][7] += p2 * vbb.w;
            o[3][0] += p3 * va.x; o[3][1] += p3 * va.y; o[3][2] += p3 * va.z; o[3][3] += p3 * va.w;
            o[3][4] += p3 * vbb.x; o[3][5] += p3 * vbb.y; o[3][6] += p3 * vbb.z; o[3][7] += p3 * vbb.w;
        }
    }

    // Normalize + write out: g_att[s, h*128 + d]
#pragma unroll
    for (int i = 0; i < 4; i++) {
        float inv = 1.f / l[i];
        float* dst = &g_att[((size_t)(qt * 64 + ty * 4 + i)) * DMODEL + h * HDIM + tx * 8];
        *(float4*)dst = make_float4(o[i][0] * inv, o[i][1] * inv, o[i][2] * inv, o[i][3] * inv);
        *(float4*)(dst + 4) = make_float4(o[i][4] * inv, o[i][5] * inv, o[i][6] * inv, o[i][7] * inv);
    }
}

// ---------------------------------------------------------------------------
// Launch. Inputs (metadata order): x, wq, wk, wv, wo, freqs_cos, freqs_sin,
// mask, cache_k, cache_v, start_pos. mask/cache/start_pos are dead
// (start_pos==0, causal structure known, caches zero-initialized + only the
// freshly-written region is read back).
// ---------------------------------------------------------------------------
extern "C" void kernel_launch(void* const* d_in, const int* in_sizes, int n_in,
                              void* d_out, int out_size) {
    const float* x  = (const float*)d_in[0];
    const float* wq = (const float*)d_in[1];
    const float* wk = (const float*)d_in[2];
    const float* wv = (const float*)d_in[3];
    const float* wo = (const float*)d_in[4];
    const float* fc = (const float*)d_in[5];
    const float* fs = (const float*)d_in[6];
    float* out = (float*)d_out;

    float *qb, *kb, *vb, *ab;
    cudaGetSymbolAddress((void**)&qb, g_q);
    cudaGetSymbolAddress((void**)&kb, g_k);
    cudaGetSymbolAddress((void**)&vb, g_v);
    cudaGetSymbolAddress((void**)&ab, g_att);

    dim3 blk(256);
    sgemm_kernel<DMODEL, DMODEL><<<dim3(32, 16), blk>>>(x, wq, qb);
    sgemm_kernel<KVDIM,  DMODEL><<<dim3(8, 16),  blk>>>(x, wk, kb);
    sgemm_kernel<KVDIM,  DMODEL><<<dim3(8, 16),  blk>>>(x, wv, vb);

    rope_kernel<<<(SEQ * NH * 64 + 255) / 256, 256>>>(qb, fc, fs, NH);
    rope_kernel<<<(SEQ * NKV * 64 + 255) / 256, 256>>>(kb, fc, fs, NKV);

    const int FLASH_SMEM = (64 * 129 + 64 * 129 + 64 * 128 + 64 * 65) * 4;  // 115,456 B
    cudaFuncSetAttribute(flash_kernel, cudaFuncAttributeMaxDynamicSharedMemorySize, FLASH_SMEM);
    flash_kernel<<<dim3(SEQ / 64, NH), 256, FLASH_SMEM>>>();

    sgemm_kernel<DMODEL, DMODEL><<<dim3(32, 16), blk>>>(ab, wo, out);
}

// round 10
// speedup vs baseline: 2.2787x; 2.2787x over previous
#include <cuda_runtime.h>
#include <math_constants.h>

#define SEQ    2048
#define DMODEL 4096
#define NH     32
#define NKV    8
#define HDIM   128
#define KVDIM  (NKV*HDIM)   // 1024

// Scratch (no allocation allowed) — ~84 MB total
__device__ float g_q[SEQ * DMODEL];
__device__ float g_k[SEQ * KVDIM];
__device__ float g_v[SEQ * KVDIM];
__device__ float g_att[SEQ * DMODEL];

// ---------------------------------------------------------------------------
// 3xTF32 tensor-core GEMM: C[M,N] = A[M,K] @ B[K,N], row-major fp32 in/out.
// CTA tile 128x128, BK=32, 256 threads = 8 warps (2 m x 4 n), warp tile 64x32.
// Each fp32 input split hi/lo in tf32; acc += Ah*Bh + Ah*Bl + Al*Bh (fp32 acc).
// Smem pitches: A [m][PA=36] and B [k][PB=136] make every fragment gather and
// every tile store conflict-free (bank index is a lane permutation).
// ---------------------------------------------------------------------------
#define PA 36
#define PB 136
#define GEMM_SMEM ((128*PA*2 + 32*PB*2) * 4)   // 71,680 B

__device__ __forceinline__ unsigned f2tf(float x) {
    unsigned r;
    asm("cvt.rna.tf32.f32 %0, %1;" : "=r"(r) : "f"(x));
    return r;
}

__device__ __forceinline__ void mma_tf32(float* d, const unsigned* a, const unsigned* b) {
    asm volatile(
        "mma.sync.aligned.m16n8k8.row.col.f32.tf32.tf32.f32 "
        "{%0,%1,%2,%3}, {%4,%5,%6,%7}, {%8,%9}, {%0,%1,%2,%3};\n"
        : "+f"(d[0]), "+f"(d[1]), "+f"(d[2]), "+f"(d[3])
        : "r"(a[0]), "r"(a[1]), "r"(a[2]), "r"(a[3]), "r"(b[0]), "r"(b[1]));
}

template <int N, int K>
__global__ __launch_bounds__(256) void gemm_tc(const float* __restrict__ A,
                                               const float* __restrict__ B,
                                               float* __restrict__ C) {
    extern __shared__ float sm[];
    float* Ah = sm;                 // [128][PA]
    float* Al = Ah + 128 * PA;
    float* Bh = Al + 128 * PA;      // [32][PB]
    float* Bl = Bh + 32 * PB;

    const int tid = threadIdx.x;
    const int lane = tid & 31, warp = tid >> 5;
    const int wm = warp & 1, wn = warp >> 1;           // 2 x 4 warp grid
    const int lg = lane >> 2, lt = lane & 3;           // groupID, tid-in-group

    float acc[4][4][4];
#pragma unroll
    for (int mf = 0; mf < 4; mf++)
#pragma unroll
        for (int nf = 0; nf < 4; nf++)
#pragma unroll
            for (int r = 0; r < 4; r++) acc[mf][nf][r] = 0.f;

    // global load bases: A rows of 128B (8 lanes/row), B rows of 512B (32 lanes/row)
    const float* Ag = A + ((size_t)(blockIdx.y * 128 + (tid >> 3))) * K + ((tid & 7) << 2);
    const float* Bg = B + (size_t)(tid >> 5) * N + blockIdx.x * 128 + ((tid & 31) << 2);

    for (int kt = 0; kt < K; kt += 32) {
        // --- stage A tile (128m x 32k): 4 iters of 32 rows, split hi/lo ---
#pragma unroll
        for (int it = 0; it < 4; it++) {
            float4 v = *(const float4*)(Ag + (size_t)(it * 32) * K + kt);
            const int m = (tid >> 3) + it * 32;
            float* dh = &Ah[m * PA + ((tid & 7) << 2)];
            float* dl = &Al[m * PA + ((tid & 7) << 2)];
            float hx = __uint_as_float(f2tf(v.x));
            float hy = __uint_as_float(f2tf(v.y));
            float hz = __uint_as_float(f2tf(v.z));
            float hw = __uint_as_float(f2tf(v.w));
            dh[0] = hx; dh[1] = hy; dh[2] = hz; dh[3] = hw;
            dl[0] = __uint_as_float(f2tf(v.x - hx));
            dl[1] = __uint_as_float(f2tf(v.y - hy));
            dl[2] = __uint_as_float(f2tf(v.z - hz));
            dl[3] = __uint_as_float(f2tf(v.w - hw));
        }
        // --- stage B tile (32k x 128n): 4 iters of 8 k-rows ---
#pragma unroll
        for (int it = 0; it < 4; it++) {
            float4 v = *(const float4*)(Bg + (size_t)(kt + it * 8) * N);
            const int k = (tid >> 5) + it * 8;
            float hx = __uint_as_float(f2tf(v.x));
            float hy = __uint_as_float(f2tf(v.y));
            float hz = __uint_as_float(f2tf(v.z));
            float hw = __uint_as_float(f2tf(v.w));
            *(float4*)&Bh[k * PB + ((tid & 31) << 2)] = make_float4(hx, hy, hz, hw);
            *(float4*)&Bl[k * PB + ((tid & 31) << 2)] = make_float4(
                __uint_as_float(f2tf(v.x - hx)), __uint_as_float(f2tf(v.y - hy)),
                __uint_as_float(f2tf(v.z - hz)), __uint_as_float(f2tf(v.w - hw)));
        }
        __syncthreads();

        // --- compute: 4 k8 chunks, 3-pass tf32 mma ---
#pragma unroll
        for (int ch = 0; ch < 4; ch++) {
            const int k0 = (ch << 3) + lt;
            const int n0 = wn * 32 + lg;
            unsigned bh[4][2], bl[4][2];
#pragma unroll
            for (int nf = 0; nf < 4; nf++) {
                const float* p = &Bh[k0 * PB + n0 + nf * 8];
                bh[nf][0] = __float_as_uint(p[0]);
                bh[nf][1] = __float_as_uint(p[4 * PB]);
                const float* q = &Bl[k0 * PB + n0 + nf * 8];
                bl[nf][0] = __float_as_uint(q[0]);
                bl[nf][1] = __float_as_uint(q[4 * PB]);
            }
#pragma unroll
            for (int mf = 0; mf < 4; mf++) {
                const int r = wm * 64 + mf * 16 + lg;
                const float* p = &Ah[r * PA + (ch << 3) + lt];
                const float* q = &Al[r * PA + (ch << 3) + lt];
                unsigned ah[4], al[4];
                ah[0] = __float_as_uint(p[0]);
                ah[1] = __float_as_uint(p[8 * PA]);
                ah[2] = __float_as_uint(p[4]);
                ah[3] = __float_as_uint(p[8 * PA + 4]);
                al[0] = __float_as_uint(q[0]);
                al[1] = __float_as_uint(q[8 * PA]);
                al[2] = __float_as_uint(q[4]);
                al[3] = __float_as_uint(q[8 * PA + 4]);
#pragma unroll
                for (int nf = 0; nf < 4; nf++) {
                    mma_tf32(acc[mf][nf], ah, bh[nf]);
                    mma_tf32(acc[mf][nf], ah, bl[nf]);
                    mma_tf32(acc[mf][nf], al, bh[nf]);
                }
            }
        }
        __syncthreads();
    }

    // --- epilogue: c0,c1 at (row, 2*lt), c2,c3 at (row+8, 2*lt) ---
    const int r0 = blockIdx.y * 128 + wm * 64 + lg;
    const int c0 = blockIdx.x * 128 + wn * 32 + (lt << 1);
#pragma unroll
    for (int mf = 0; mf < 4; mf++)
#pragma unroll
        for (int nf = 0; nf < 4; nf++) {
            float* p = C + (size_t)(r0 + mf * 16) * N + c0 + nf * 8;
            *(float2*)p = make_float2(acc[mf][nf][0], acc[mf][nf][1]);
            *(float2*)(p + (size_t)8 * N) = make_float2(acc[mf][nf][2], acc[mf][nf][3]);
        }
}

// ---------------------------------------------------------------------------
// RoPE (interleaved pairs)
// ---------------------------------------------------------------------------
__global__ void rope_kernel(float* __restrict__ t, const float* __restrict__ cs,
                            const float* __restrict__ sn, int nheads) {
    int idx = blockIdx.x * blockDim.x + threadIdx.x;
    int total = SEQ * nheads * (HDIM / 2);
    if (idx >= total) return;
    int d = idx & 63;
    int h = (idx >> 6) % nheads;
    int s = idx / (64 * nheads);
    float c = cs[s * 64 + d];
    float si = sn[s * 64 + d];
    float2* p = (float2*)(t + ((size_t)s * nheads + h) * HDIM) + d;
    float2 v = *p;
    *p = make_float2(v.x * c - v.y * si, v.y * c + v.x * si);
}

// ---------------------------------------------------------------------------
// Flash attention, fp32 (unchanged from passing R5 kernel)
// ---------------------------------------------------------------------------
__global__ __launch_bounds__(256) void flash_kernel() {
    extern __shared__ float sm[];
    float* Qs = sm;                 // 64 x 129
    float* Ks = Qs + 64 * 129;      // 64 x 129
    float* Vs = Ks + 64 * 129;      // 64 x 128
    float* Ps = Vs + 64 * 128;      // 64 x 65

    const int qt = blockIdx.x;
    const int h = blockIdx.y;
    const int kvh = h & (NKV - 1);
    const int tid = threadIdx.x;
    const int ty = tid >> 4, tx = tid & 15;
    const float scale = 0.08838834764831845f;  // 1/sqrt(128)

#pragma unroll
    for (int i = 0; i < 8; i++) {
        int fi = i * 256 + tid;
        int r = fi >> 5, c = (fi & 31) << 2;
        float4 q4 = *(const float4*)&g_q[((size_t)(qt * 64 + r)) * DMODEL + h * HDIM + c];
        float* dq = &Qs[r * 129 + c];
        dq[0] = q4.x * scale; dq[1] = q4.y * scale;
        dq[2] = q4.z * scale; dq[3] = q4.w * scale;
    }

    float o[4][8];
    float m[4], l[4];
#pragma unroll
    for (int i = 0; i < 4; i++) {
        m[i] = -CUDART_INF_F;
        l[i] = 0.f;
#pragma unroll
        for (int j = 0; j < 8; j++) o[i][j] = 0.f;
    }

    for (int kt = 0; kt <= qt; kt++) {
        __syncthreads();
#pragma unroll
        for (int i = 0; i < 8; i++) {
            int fi = i * 256 + tid;
            int r = fi >> 5, c = (fi & 31) << 2;
            size_t gidx = ((size_t)(kt * 64 + r)) * KVDIM + kvh * HDIM + c;
            float4 k4 = *(const float4*)&g_k[gidx];
            float* dk = &Ks[r * 129 + c];
            dk[0] = k4.x; dk[1] = k4.y; dk[2] = k4.z; dk[3] = k4.w;
            *(float4*)&Vs[r * 128 + c] = *(const float4*)&g_v[gidx];
        }
        __syncthreads();

        float s[4][4];
#pragma unroll
        for (int i = 0; i < 4; i++)
#pragma unroll
            for (int j = 0; j < 4; j++) s[i][j] = 0.f;

        const float* q0 = &Qs[(ty * 4 + 0) * 129];
        const float* q1 = q0 + 129;
        const float* q2 = q1 + 129;
        const float* q3 = q2 + 129;
        const float* k0 = &Ks[(tx + 0) * 129];
        const float* k1 = &Ks[(tx + 16) * 129];
        const float* k2 = &Ks[(tx + 32) * 129];
        const float* k3 = &Ks[(tx + 48) * 129];
#pragma unroll 8
        for (int d = 0; d < 128; d++) {
            float a0 = q0[d], a1 = q1[d], a2 = q2[d], a3 = q3[d];
            float b0 = k0[d], b1 = k1[d], b2 = k2[d], b3 = k3[d];
            s[0][0] += a0 * b0; s[0][1] += a0 * b1; s[0][2] += a0 * b2; s[0][3] += a0 * b3;
            s[1][0] += a1 * b0; s[1][1] += a1 * b1; s[1][2] += a1 * b2; s[1][3] += a1 * b3;
            s[2][0] += a2 * b0; s[2][1] += a2 * b1; s[2][2] += a2 * b2; s[2][3] += a2 * b3;
            s[3][0] += a3 * b0; s[3][1] += a3 * b1; s[3][2] += a3 * b2; s[3][3] += a3 * b3;
        }

        if (kt == qt) {
#pragma unroll
            for (int i = 0; i < 4; i++)
#pragma unroll
                for (int j = 0; j < 4; j++)
                    if (tx + 16 * j > ty * 4 + i) s[i][j] = -CUDART_INF_F;
        }

#pragma unroll
        for (int i = 0; i < 4; i++) {
            float mx = fmaxf(fmaxf(s[i][0], s[i][1]), fmaxf(s[i][2], s[i][3]));
            mx = fmaxf(mx, __shfl_xor_sync(0xffffffffu, mx, 1, 16));
            mx = fmaxf(mx, __shfl_xor_sync(0xffffffffu, mx, 2, 16));
            mx = fmaxf(mx, __shfl_xor_sync(0xffffffffu, mx, 4, 16));
            mx = fmaxf(mx, __shfl_xor_sync(0xffffffffu, mx, 8, 16));
            float mn = fmaxf(m[i], mx);
            float corr = __expf(m[i] - mn);
            m[i] = mn;
            float sum = 0.f;
#pragma unroll
            for (int j = 0; j < 4; j++) {
                float p = __expf(s[i][j] - mn);
                s[i][j] = p;
                sum += p;
            }
            sum += __shfl_xor_sync(0xffffffffu, sum, 1, 16);
            sum += __shfl_xor_sync(0xffffffffu, sum, 2, 16);
            sum += __shfl_xor_sync(0xffffffffu, sum, 4, 16);
            sum += __shfl_xor_sync(0xffffffffu, sum, 8, 16);
            l[i] = l[i] * corr + sum;
#pragma unroll
            for (int j = 0; j < 8; j++) o[i][j] *= corr;
            float* pr = &Ps[(ty * 4 + i) * 65];
            pr[tx] = s[i][0];
            pr[tx + 16] = s[i][1];
            pr[tx + 32] = s[i][2];
            pr[tx + 48] = s[i][3];
        }
        __syncthreads();

        const float* vb = &Vs[tx * 8];
        const float* p0r = &Ps[(ty * 4 + 0) * 65];
        const float* p1r = p0r + 65;
        const float* p2r = p1r + 65;
        const float* p3r = p2r + 65;
#pragma unroll 4
        for (int c = 0; c < 64; c++) {
            float p0 = p0r[c], p1 = p1r[c], p2 = p2r[c], p3 = p3r[c];
            float4 va = *(const float4*)&vb[c * 128];
            float4 vbb = *(const float4*)&vb[c * 128 + 4];
            o[0][0] += p0 * va.x; o[0][1] += p0 * va.y; o[0][2] += p0 * va.z; o[0][3] += p0 * va.w;
            o[0][4] += p0 * vbb.x; o[0][5] += p0 * vbb.y; o[0][6] += p0 * vbb.z; o[0][7] += p0 * vbb.w;
            o[1][0] += p1 * va.x; o[1][1] += p1 * va.y; o[1][2] += p1 * va.z; o[1][3] += p1 * va.w;
            o[1][4] += p1 * vbb.x; o[1][5] += p1 * vbb.y; o[1][6] += p1 * vbb.z; o[1][7] += p1 * vbb.w;
            o[2][0] += p2 * va.x; o[2][1] += p2 * va.y; o[2][2] += p2 * va.z; o[2][3] += p2 * va.w;
            o[2][4] += p2 * vbb.x; o[2][5] += p2 * vbb.y; o[2][6] += p2 * vbb.z; o[2][7] += p2 * vbb.w;
            o[3][0] += p3 * va.x; o[3][1] += p3 * va.y; o[3][2] += p3 * va.z; o[3][3] += p3 * va.w;
            o[3][4] += p3 * vbb.x; o[3][5] += p3 * vbb.y; o[3][6] += p3 * vbb.z; o[3][7] += p3 * vbb.w;
        }
    }

#pragma unroll
    for (int i = 0; i < 4; i++) {
        float inv = 1.f / l[i];
        float* dst = &g_att[((size_t)(qt * 64 + ty * 4 + i)) * DMODEL + h * HDIM + tx * 8];
        *(float4*)dst = make_float4(o[i][0] * inv, o[i][1] * inv, o[i][2] * inv, o[i][3] * inv);
        *(float4*)(dst + 4) = make_float4(o[i][4] * inv, o[i][5] * inv, o[i][6] * inv, o[i][7] * inv);
    }
}

// ---------------------------------------------------------------------------
// Launch. Inputs: x, wq, wk, wv, wo, freqs_cos, freqs_sin, mask, cache_k,
// cache_v, start_pos (mask/caches/start_pos dead: start_pos==0, causal known).
// ---------------------------------------------------------------------------
extern "C" void kernel_launch(void* const* d_in, const int* in_sizes, int n_in,
                              void* d_out, int out_size) {
    const float* x  = (const float*)d_in[0];
    const float* wq = (const float*)d_in[1];
    const float* wk = (const float*)d_in[2];
    const float* wv = (const float*)d_in[3];
    const float* wo = (const float*)d_in[4];
    const float* fc = (const float*)d_in[5];
    const float* fs = (const float*)d_in[6];
    float* out = (float*)d_out;

    float *qb, *kb, *vb, *ab;
    cudaGetSymbolAddress((void**)&qb, g_q);
    cudaGetSymbolAddress((void**)&kb, g_k);
    cudaGetSymbolAddress((void**)&vb, g_v);
    cudaGetSymbolAddress((void**)&ab, g_att);

    cudaFuncSetAttribute(gemm_tc<DMODEL, DMODEL>, cudaFuncAttributeMaxDynamicSharedMemorySize, GEMM_SMEM);
    cudaFuncSetAttribute(gemm_tc<KVDIM, DMODEL>,  cudaFuncAttributeMaxDynamicSharedMemorySize, GEMM_SMEM);

    dim3 blk(256);
    gemm_tc<DMODEL, DMODEL><<<dim3(32, 16), blk, GEMM_SMEM>>>(x, wq, qb);
    gemm_tc<KVDIM,  DMODEL><<<dim3(8, 16),  blk, GEMM_SMEM>>>(x, wk, kb);
    gemm_tc<KVDIM,  DMODEL><<<dim3(8, 16),  blk, GEMM_SMEM>>>(x, wv, vb);

    rope_kernel<<<(SEQ * NH * 64 + 255) / 256, 256>>>(qb, fc, fs, NH);
    rope_kernel<<<(SEQ * NKV * 64 + 255) / 256, 256>>>(kb, fc, fs, NKV);

    const int FLASH_SMEM = (64 * 129 + 64 * 129 + 64 * 128 + 64 * 65) * 4;  // 115,456 B
    cudaFuncSetAttribute(flash_kernel, cudaFuncAttributeMaxDynamicSharedMemorySize, FLASH_SMEM);
    flash_kernel<<<dim3(SEQ / 64, NH), 256, FLASH_SMEM>>>();

    gemm_tc<DMODEL, DMODEL><<<dim3(32, 16), blk, GEMM_SMEM>>>(ab, wo, out);
}